// round 4
// baseline (speedup 1.0000x reference)
#include <cuda_runtime.h>
#include <cstdint>
#include <algorithm>

// Problem constants (fixed by dataset shapes)
#define BATCH 4
#define NV    4096
#define NC    128
#define NS    1024   // NV / POOLING_RATE
#define KNBR  4
#define PLF   (NV * 3)        // floats per (b,c) feature plane = 12288
#define PLB   (PLF * 4)       // bytes per plane = 49152

typedef unsigned long long ull;

struct Samp { int s[NS]; };   // 4KB by-value kernel parameter

// -------- device scratch (no allocation allowed) --------
__device__ __align__(16) int g_nbr[BATCH * NS * KNBR];

// -------- JAX threefry2x32 (20 rounds), host-usable --------
__host__ __device__ __forceinline__ void threefry2x32(
    uint32_t k0, uint32_t k1, uint32_t x0, uint32_t x1,
    uint32_t* o0, uint32_t* o1)
{
    uint32_t ks2 = k0 ^ k1 ^ 0x1BD11BDAu;
    x0 += k0; x1 += k1;
#define TF_ROT(x, r) (((x) << (r)) | ((x) >> (32 - (r))))
#define TF_R4(a, b, c, d)                       \
    x0 += x1; x1 = TF_ROT(x1, a); x1 ^= x0;     \
    x0 += x1; x1 = TF_ROT(x1, b); x1 ^= x0;     \
    x0 += x1; x1 = TF_ROT(x1, c); x1 ^= x0;     \
    x0 += x1; x1 = TF_ROT(x1, d); x1 ^= x0;
    TF_R4(13, 15, 26, 6);  x0 += k1;  x1 += ks2 + 1u;
    TF_R4(17, 29, 16, 24); x0 += ks2; x1 += k0 + 2u;
    TF_R4(13, 15, 26, 6);  x0 += k0;  x1 += k1 + 3u;
    TF_R4(17, 29, 16, 24); x0 += k1;  x1 += ks2 + 4u;
    TF_R4(13, 15, 26, 6);  x0 += ks2; x1 += k0 + 5u;
#undef TF_R4
#undef TF_ROT
    *o0 = x0; *o1 = x1;
}

// ======================= K_knn ==============================================
// Each warp owns 4 queries and scans all 4096 points (top-5, drop min=self).
// block = 128 threads (4 warps = 16 queries); grid = 4*64 = 256 blocks.
__global__ __launch_bounds__(128) void knn_kernel(const float* __restrict__ Vtx,
                                                  Samp smp)
{
    __shared__ float sx[NV], sy[NV], sz[NV];  // 48KB
    int b = blockIdx.x >> 6;
    const float* vb = Vtx + b * NV * 3;

    // stage vertices: 4 points (3 float4) per thread-iteration
    {
        const float4* vb4 = (const float4*)vb;
        for (int c = threadIdx.x; c < NV / 4; c += 128) {
            float4 a = vb4[3 * c], d4 = vb4[3 * c + 1], e4 = vb4[3 * c + 2];
            int p = 4 * c;
            sx[p]     = a.x;  sy[p]     = a.y;  sz[p]     = a.z;
            sx[p + 1] = a.w;  sy[p + 1] = d4.x; sz[p + 1] = d4.y;
            sx[p + 2] = d4.z; sy[p + 2] = d4.w; sz[p + 2] = e4.x;
            sx[p + 3] = e4.y; sy[p + 3] = e4.z; sz[p + 3] = e4.w;
        }
    }
    __syncthreads();

    int warp = threadIdx.x >> 5;
    int lane = threadIdx.x & 31;
    int s0 = ((blockIdx.x & 63) << 4) + (warp << 2);   // first of 4 queries

    float qx[4], qy[4], qz[4], qq[4];
#pragma unroll
    for (int qi = 0; qi < 4; ++qi) {
        int n = smp.s[s0 + qi];
        qx[qi] = sx[n]; qy[qi] = sy[n]; qz[qi] = sz[n];
        qq[qi] = qx[qi] * qx[qi] + qy[qi] * qy[qi] + qz[qi] * qz[qi];
    }

    // per-lane sorted top-5 per query; self included (d=0 => global min)
    ull k0[4], k1[4], k2[4], k3[4], k4[4];
#pragma unroll
    for (int qi = 0; qi < 4; ++qi)
        k0[qi] = k1[qi] = k2[qi] = k3[qi] = k4[qi] = ~0ULL;

    for (int m = lane; m < NV; m += 32) {
        float xm = sx[m], ym = sy[m], zm = sz[m];
        float qm = xm * xm + ym * ym + zm * zm;
#pragma unroll
        for (int qi = 0; qi < 4; ++qi) {
            float inner = qx[qi] * xm + qy[qi] * ym + qz[qi] * zm;
            float d = (-2.0f * inner + qm) + qq[qi];   // matches reference assoc
            ull key = ((ull)__float_as_uint(d) << 32) | (unsigned)m;
            if (key < k4[qi]) {
                if (key < k2[qi]) {
                    k4[qi] = k3[qi]; k3[qi] = k2[qi];
                    if (key < k1[qi]) {
                        k2[qi] = k1[qi];
                        if (key < k0[qi]) { k1[qi] = k0[qi]; k0[qi] = key; }
                        else k1[qi] = key;
                    } else k2[qi] = key;
                } else {
                    if (key < k3[qi]) { k4[qi] = k3[qi]; k3[qi] = key; }
                    else k4[qi] = key;
                }
            }
        }
    }

    // warp merge per query: pop global min 5 times; entry 0 is self -> dropped
#pragma unroll
    for (int qi = 0; qi < 4; ++qi) {
        int res[5];
#pragma unroll
        for (int t = 0; t < 5; ++t) {
            ull mn = k0[qi];
#pragma unroll
            for (int off = 16; off; off >>= 1) {
                ull o = __shfl_xor_sync(0xffffffffu, mn, off);
                mn = (o < mn) ? o : mn;
            }
            if (k0[qi] == mn) {   // unique key -> exactly one lane shifts
                k0[qi] = k1[qi]; k1[qi] = k2[qi];
                k2[qi] = k3[qi]; k3[qi] = k4[qi]; k4[qi] = ~0ULL;
            }
            res[t] = (int)(unsigned)(mn & 0xffffffffULL);
        }
        if (lane == 0) {
            int4 w = make_int4(res[1], res[2], res[3], res[4]);
            *(int4*)&g_nbr[(b * NS + (s0 + qi)) * KNBR] = w;
        }
    }
}

// ======================= K_pool =============================================
__device__ __forceinline__ void mbar_init(void* mbar, unsigned count)
{
    unsigned a = (unsigned)__cvta_generic_to_shared(mbar);
    asm volatile("mbarrier.init.shared.b64 [%0], %1;" :: "r"(a), "r"(count) : "memory");
}
__device__ __forceinline__ void mbar_expect_tx(void* mbar, unsigned bytes)
{
    unsigned a = (unsigned)__cvta_generic_to_shared(mbar);
    asm volatile("mbarrier.arrive.expect_tx.shared.b64 _, [%0], %1;"
                 :: "r"(a), "r"(bytes) : "memory");
}
__device__ __forceinline__ void bulk_g2s(void* dst, const void* src,
                                         unsigned bytes, void* mbar)
{
    unsigned d = (unsigned)__cvta_generic_to_shared(dst);
    unsigned m = (unsigned)__cvta_generic_to_shared(mbar);
    asm volatile(
        "cp.async.bulk.shared::cta.global.mbarrier::complete_tx::bytes "
        "[%0], [%1], %2, [%3];"
        :: "r"(d), "l"(src), "r"(bytes), "r"(m) : "memory");
}
__device__ __forceinline__ void mbar_wait(void* mbar, unsigned parity)
{
    unsigned a = (unsigned)__cvta_generic_to_shared(mbar);
    asm volatile(
        "{\n\t.reg .pred P;\n\t"
        "W%=:\n\t"
        "mbarrier.try_wait.parity.acquire.cta.shared::cta.b64 P, [%0], %1, 0x989680;\n\t"
        "@P bra.uni D%=;\n\t"
        "bra.uni W%=;\n\t"
        "D%=:\n\t}"
        :: "r"(a), "r"(parity) : "memory");
}

// gather max over 4 neighbors from one staged plane
__device__ __forceinline__ void pool_gather(const float* __restrict__ sf,
                                            int pl, float* __restrict__ out)
{
    int b = pl >> 7, c = pl & 127;
    float* fout = out + BATCH * NS * 3;  // feature_map_pool region
#pragma unroll
    for (int r = 0; r < NS / 256; ++r) {
        int t = r * 256 + threadIdx.x;
        int4 nb = *(const int4*)&g_nbr[(b * NS + t) * KNBR];
        int j0 = nb.x * 3, j1 = nb.y * 3, j2 = nb.z * 3, j3 = nb.w * 3;
        float o0 = fmaxf(fmaxf(sf[j0],     sf[j1]),     fmaxf(sf[j2],     sf[j3]));
        float o1 = fmaxf(fmaxf(sf[j0 + 1], sf[j1 + 1]), fmaxf(sf[j2 + 1], sf[j3 + 1]));
        float o2 = fmaxf(fmaxf(sf[j0 + 2], sf[j1 + 2]), fmaxf(sf[j2 + 2], sf[j3 + 2]));
        size_t ob = ((size_t)(b * NC + c) * NS + t) * 3;
        fout[ob] = o0; fout[ob + 1] = o1; fout[ob + 2] = o2;
    }
}

// 2 planes per block via cp.async.bulk (TMA), double-buffered
// grid = 256 blocks, block = 256, dynamic smem = 96KB
__global__ __launch_bounds__(256) void pool_kernel(const float* __restrict__ F,
                                                   const float* __restrict__ Vtx,
                                                   float* __restrict__ out,
                                                   Samp smp)
{
    extern __shared__ __align__(128) float sf[];   // [2 * PLF]
    __shared__ __align__(8) ull mbar[2];

    int pl0 = blockIdx.x * 2;
    if (threadIdx.x == 0) {
        mbar_init(&mbar[0], 1);
        mbar_init(&mbar[1], 1);
    }
    __syncthreads();
    if (threadIdx.x == 0) {
        mbar_expect_tx(&mbar[0], PLB);
        bulk_g2s(sf,       F + (size_t)pl0 * PLF,       PLB, &mbar[0]);
        mbar_expect_tx(&mbar[1], PLB);
        bulk_g2s(sf + PLF, F + (size_t)(pl0 + 1) * PLF, PLB, &mbar[1]);
    }

    mbar_wait(&mbar[0], 0);
    pool_gather(sf, pl0, out);

    mbar_wait(&mbar[1], 0);
    pool_gather(sf + PLF, pl0 + 1, out);

    // blocks owning plane c==0 also emit vertices_pool (b,1024,3)
    if ((pl0 & 127) == 0) {
        int b = pl0 >> 7;
        const float* vb = Vtx + b * NV * 3;
        for (int t = threadIdx.x; t < NS * 3; t += 256) {
            int s = t / 3, d = t - 3 * s;
            out[(b * NS + s) * 3 + d] = vb[smp.s[s] * 3 + d];
        }
    }
}

// ======================= host entry =========================================
extern "C" void kernel_launch(void* const* d_in, const int* in_sizes, int n_in,
                              void* d_out, int out_size)
{
    const float* Vtx;
    const float* F;
    if (in_sizes[0] == BATCH * NV * 3) {
        Vtx = (const float*)d_in[0];
        F   = (const float*)d_in[1];
    } else {
        Vtx = (const float*)d_in[1];
        F   = (const float*)d_in[0];
    }

    // ---- host-side permutation (pure arithmetic; runs at capture time) ----
    // jax.random.key(42), two partitionable/foldlike splits:
    //   split(k): keys[i] = cipher(k; 0, i); carry = cipher(k;0,0), sub = cipher(k;0,1)
    // random_bits(sub,32,(n,)): bits[i] = w0^w1 of cipher(sub; 0, i)
    uint32_t k10, k11, sub_lo[2], sub_hi[2];
    threefry2x32(0u, 42u, 0u, 0u, &k10, &k11);             // round-1 carry key
    threefry2x32(0u, 42u, 0u, 1u, &sub_lo[0], &sub_hi[0]); // round-1 subkey
    threefry2x32(k10, k11, 0u, 1u, &sub_lo[1], &sub_hi[1]);// round-2 subkey

    static ull pk[NV];
    static int rk[2][NV];
    for (int r = 0; r < 2; ++r) {
        for (int i = 0; i < NV; ++i) {
            uint32_t w0, w1;
            threefry2x32(sub_lo[r], sub_hi[r], 0u, (uint32_t)i, &w0, &w1);
            pk[i] = ((ull)(w0 ^ w1) << 32) | (uint32_t)i;
        }
        std::sort(pk, pk + NV);   // index in low bits -> stable rank
        for (int j = 0; j < NV; ++j) rk[r][(uint32_t)pk[j]] = j;
    }
    static Samp h_samp;
    for (int i = 0; i < NV; ++i) {
        int pos = rk[1][rk[0][i]];
        if (pos < NS) h_samp.s[pos] = i;
    }

    cudaFuncSetAttribute(pool_kernel,
                         cudaFuncAttributeMaxDynamicSharedMemorySize,
                         2 * PLF * (int)sizeof(float));

    knn_kernel<<<256, 128>>>(Vtx, h_samp);
    pool_kernel<<<256, 256, 2 * PLF * sizeof(float)>>>(F, Vtx, (float*)d_out, h_samp);
}

// round 5
// speedup vs baseline: 1.1880x; 1.1880x over previous
#include <cuda_runtime.h>
#include <cstdint>
#include <algorithm>

// Problem constants (fixed by dataset shapes)
#define BATCH 4
#define NV    4096
#define NC    128
#define NS    1024   // NV / POOLING_RATE
#define KNBR  4
#define PLF   (NV * 3)        // floats per (b,c) feature plane = 12288

typedef unsigned long long ull;

struct Samp { int s[NS]; };   // 4KB by-value kernel parameter

// -------- device scratch (no allocation allowed) --------
__device__ __align__(16) int g_nbr[BATCH * NS * KNBR];

// -------- JAX threefry2x32 (20 rounds), host-usable --------
__host__ __device__ __forceinline__ void threefry2x32(
    uint32_t k0, uint32_t k1, uint32_t x0, uint32_t x1,
    uint32_t* o0, uint32_t* o1)
{
    uint32_t ks2 = k0 ^ k1 ^ 0x1BD11BDAu;
    x0 += k0; x1 += k1;
#define TF_ROT(x, r) (((x) << (r)) | ((x) >> (32 - (r))))
#define TF_R4(a, b, c, d)                       \
    x0 += x1; x1 = TF_ROT(x1, a); x1 ^= x0;     \
    x0 += x1; x1 = TF_ROT(x1, b); x1 ^= x0;     \
    x0 += x1; x1 = TF_ROT(x1, c); x1 ^= x0;     \
    x0 += x1; x1 = TF_ROT(x1, d); x1 ^= x0;
    TF_R4(13, 15, 26, 6);  x0 += k1;  x1 += ks2 + 1u;
    TF_R4(17, 29, 16, 24); x0 += ks2; x1 += k0 + 2u;
    TF_R4(13, 15, 26, 6);  x0 += k0;  x1 += k1 + 3u;
    TF_R4(17, 29, 16, 24); x0 += k1;  x1 += ks2 + 4u;
    TF_R4(13, 15, 26, 6);  x0 += ks2; x1 += k0 + 5u;
#undef TF_R4
#undef TF_ROT
    *o0 = x0; *o1 = x1;
}

// ======================= K_knn ==============================================
// 4 queries per warp. Phase 1: float-only per-lane top-5 (FMNMX bubble) ->
// exact warp threshold t >= d_(5). Phase 2: rescan, compact hits (d <= t) to
// smem, rank <=32 candidates by packed (monotone dist bits, idx) key.
// block = 128 (4 warps = 16 queries); grid = 4 * 64 = 256 blocks.
// dynamic smem: sx/sy/sz (48KB) + buf[16][32] ull (4KB) + cnt[16]
__global__ __launch_bounds__(128) void knn_kernel(const float* __restrict__ Vtx,
                                                  Samp smp)
{
    extern __shared__ __align__(16) float smem[];
    float* sx = smem;
    float* sy = sx + NV;
    float* sz = sy + NV;
    ull*   buf = (ull*)(sz + NV);        // [16][32]
    int*   cnt = (int*)(buf + 16 * 32);  // [16]

    if (threadIdx.x < 16) cnt[threadIdx.x] = 0;

    int b = blockIdx.x >> 6;
    const float* vb = Vtx + b * NV * 3;
    {
        const float4* vb4 = (const float4*)vb;
        for (int c = threadIdx.x; c < NV / 4; c += 128) {
            float4 a = vb4[3 * c], d4 = vb4[3 * c + 1], e4 = vb4[3 * c + 2];
            int p = 4 * c;
            sx[p]     = a.x;  sy[p]     = a.y;  sz[p]     = a.z;
            sx[p + 1] = a.w;  sy[p + 1] = d4.x; sz[p + 1] = d4.y;
            sx[p + 2] = d4.z; sy[p + 2] = d4.w; sz[p + 2] = e4.x;
            sx[p + 3] = e4.y; sy[p + 3] = e4.z; sz[p + 3] = e4.w;
        }
    }
    __syncthreads();

    int warp = threadIdx.x >> 5;
    int lane = threadIdx.x & 31;
    int wq = warp << 2;                                // query slot base
    int s0 = ((blockIdx.x & 63) << 4) + wq;            // first of 4 queries

    float qx[4], qy[4], qz[4], qq[4];
#pragma unroll
    for (int qi = 0; qi < 4; ++qi) {
        int n = smp.s[s0 + qi];
        qx[qi] = sx[n]; qy[qi] = sy[n]; qz[qi] = sz[n];
        qq[qi] = qx[qi] * qx[qi] + qy[qi] * qy[qi] + qz[qi] * qz[qi];
    }

    const float INF = __int_as_float(0x7f800000);
    float kk[4][5];
#pragma unroll
    for (int qi = 0; qi < 4; ++qi)
#pragma unroll
        for (int p = 0; p < 5; ++p) kk[qi][p] = INF;

    // ---- Phase 1: values-only top-5 per lane ----
#pragma unroll 2
    for (int m = lane; m < NV; m += 32) {
        float xm = sx[m], ym = sy[m], zm = sz[m];
        float qm = xm * xm + ym * ym + zm * zm;
#pragma unroll
        for (int qi = 0; qi < 4; ++qi) {
            float inner = qx[qi] * xm + qy[qi] * ym + qz[qi] * zm;
            float d = (-2.0f * inner + qm) + qq[qi];   // matches reference assoc
            if (d < kk[qi][4]) {                       // rare-ish guard
                float c0 = fmaxf(kk[qi][0], d);
                kk[qi][0] = fminf(kk[qi][0], d);
                float c1 = fmaxf(kk[qi][1], c0);
                kk[qi][1] = fminf(kk[qi][1], c0);
                float c2 = fmaxf(kk[qi][2], c1);
                kk[qi][2] = fminf(kk[qi][2], c1);
                float c3 = fmaxf(kk[qi][3], c2);
                kk[qi][3] = fminf(kk[qi][3], c2);
                kk[qi][4] = fminf(kk[qi][4], c3);
            }
        }
    }

    // ---- merge: pop warp-min 5 times -> threshold t >= d_(5) ----
    float tq[4];
#pragma unroll
    for (int qi = 0; qi < 4; ++qi) {
        float h0 = kk[qi][0], h1 = kk[qi][1], h2 = kk[qi][2],
              h3 = kk[qi][3], h4 = kk[qi][4];
        float t = INF;
#pragma unroll
        for (int p = 0; p < 5; ++p) {
            float mn = h0;
#pragma unroll
            for (int off = 16; off; off >>= 1)
                mn = fminf(mn, __shfl_xor_sync(0xffffffffu, mn, off));
            bool pop = (h0 == mn);
            h0 = pop ? h1 : h0;
            h1 = pop ? h2 : h1;
            h2 = pop ? h3 : h2;
            h3 = pop ? h4 : h3;
            h4 = pop ? INF : h4;
            t = mn;
        }
        tq[qi] = t;
    }

    // ---- Phase 2: collect all m with d <= t ----
    for (int m = lane; m < NV; m += 32) {
        float xm = sx[m], ym = sy[m], zm = sz[m];
        float qm = xm * xm + ym * ym + zm * zm;
#pragma unroll
        for (int qi = 0; qi < 4; ++qi) {
            float inner = qx[qi] * xm + qy[qi] * ym + qz[qi] * zm;
            float d = (-2.0f * inner + qm) + qq[qi];
            if (d <= tq[qi]) {
                unsigned kb = __float_as_uint(d);
                kb ^= (kb & 0x80000000u) ? 0xffffffffu : 0x80000000u; // monotone
                ull key = ((ull)kb << 32) | (unsigned)m;
                int pos = atomicAdd(&cnt[wq + qi], 1);
                if (pos < 32) buf[(wq + qi) * 32 + pos] = key;
            }
        }
    }
    __syncwarp();

    // ---- rank candidates exactly (packed key = (dist, idx)), write 1..4 ----
#pragma unroll
    for (int qi = 0; qi < 4; ++qi) {
        int n = cnt[wq + qi];
        if (n > 32) n = 32;
        ull key = (lane < n) ? buf[(wq + qi) * 32 + lane] : ~0ULL;
        int rank = 0;
        for (int j = 0; j < n; ++j) {
            ull o = __shfl_sync(0xffffffffu, key, j);
            rank += (o < key);
        }
        if (lane < n && rank >= 1 && rank <= 4)
            g_nbr[(b * NS + (s0 + qi)) * KNBR + (rank - 1)] =
                (int)(unsigned)(key & 0xffffffffULL);
    }
}

// ======================= K_pool =============================================
// One plane per block; stage plane as padded float4 per vertex so each
// neighbor gather is a single LDS.128. grid = 512, block = 256, smem = 64KB.
__global__ __launch_bounds__(256) void pool_kernel(const float* __restrict__ F,
                                                   const float* __restrict__ Vtx,
                                                   float* __restrict__ out,
                                                   Samp smp)
{
    extern __shared__ __align__(16) float4 sf4[];   // [NV]
    int pl = blockIdx.x;
    int b = pl >> 7, c = pl & 127;
    const float* fp = F + (size_t)pl * PLF;

    for (int m = threadIdx.x; m < NV; m += 256) {
        float x = fp[3 * m], y = fp[3 * m + 1], z = fp[3 * m + 2];
        sf4[m] = make_float4(x, y, z, 0.0f);
    }
    __syncthreads();

    float* fout = out + BATCH * NS * 3;  // feature_map_pool region
#pragma unroll
    for (int r = 0; r < NS / 256; ++r) {
        int t = r * 256 + threadIdx.x;
        int4 nb = *(const int4*)&g_nbr[(b * NS + t) * KNBR];
        float4 A = sf4[nb.x], B = sf4[nb.y], C = sf4[nb.z], D = sf4[nb.w];
        float o0 = fmaxf(fmaxf(A.x, B.x), fmaxf(C.x, D.x));
        float o1 = fmaxf(fmaxf(A.y, B.y), fmaxf(C.y, D.y));
        float o2 = fmaxf(fmaxf(A.z, B.z), fmaxf(C.z, D.z));
        size_t ob = ((size_t)pl * NS + t) * 3;
        fout[ob] = o0; fout[ob + 1] = o1; fout[ob + 2] = o2;
    }

    // blocks with c==0 also emit vertices_pool (b,1024,3)
    if (c == 0) {
        const float* vb = Vtx + b * NV * 3;
        for (int t = threadIdx.x; t < NS * 3; t += 256) {
            int s = t / 3, d = t - 3 * s;
            out[(b * NS + s) * 3 + d] = vb[smp.s[s] * 3 + d];
        }
    }
}

// ======================= host entry =========================================
extern "C" void kernel_launch(void* const* d_in, const int* in_sizes, int n_in,
                              void* d_out, int out_size)
{
    const float* Vtx;
    const float* F;
    if (in_sizes[0] == BATCH * NV * 3) {
        Vtx = (const float*)d_in[0];
        F   = (const float*)d_in[1];
    } else {
        Vtx = (const float*)d_in[1];
        F   = (const float*)d_in[0];
    }

    // ---- host-side permutation (pure arithmetic; runs at capture time) ----
    uint32_t k10, k11, sub_lo[2], sub_hi[2];
    threefry2x32(0u, 42u, 0u, 0u, &k10, &k11);             // round-1 carry key
    threefry2x32(0u, 42u, 0u, 1u, &sub_lo[0], &sub_hi[0]); // round-1 subkey
    threefry2x32(k10, k11, 0u, 1u, &sub_lo[1], &sub_hi[1]);// round-2 subkey

    static ull pk[NV];
    static int rk[2][NV];
    for (int r = 0; r < 2; ++r) {
        for (int i = 0; i < NV; ++i) {
            uint32_t w0, w1;
            threefry2x32(sub_lo[r], sub_hi[r], 0u, (uint32_t)i, &w0, &w1);
            pk[i] = ((ull)(w0 ^ w1) << 32) | (uint32_t)i;
        }
        std::sort(pk, pk + NV);   // index in low bits -> stable rank
        for (int j = 0; j < NV; ++j) rk[r][(uint32_t)pk[j]] = j;
    }
    static Samp h_samp;
    for (int i = 0; i < NV; ++i) {
        int pos = rk[1][rk[0][i]];
        if (pos < NS) h_samp.s[pos] = i;
    }

    int knn_smem = (3 * NV) * (int)sizeof(float) + 16 * 32 * (int)sizeof(ull)
                 + 16 * (int)sizeof(int);
    int pool_smem = NV * (int)sizeof(float4);
    cudaFuncSetAttribute(knn_kernel,
                         cudaFuncAttributeMaxDynamicSharedMemorySize, knn_smem);
    cudaFuncSetAttribute(pool_kernel,
                         cudaFuncAttributeMaxDynamicSharedMemorySize, pool_smem);

    knn_kernel<<<256, 128, knn_smem>>>(Vtx, h_samp);
    pool_kernel<<<512, 256, pool_smem>>>(F, Vtx, (float*)d_out, h_samp);
}

// round 6
// speedup vs baseline: 2.1010x; 1.7686x over previous
#include <cuda_runtime.h>
#include <cstdint>
#include <algorithm>

// Problem constants (fixed by dataset shapes)
#define BATCH 4
#define NV    4096
#define NC    128
#define NS    1024   // NV / POOLING_RATE
#define KNBR  4
#define PLF   (NV * 3)        // floats per (b,c) feature plane = 12288
#define PLB   (PLF * 4)       // bytes per plane = 49152
#define VBB   (NV * 3 * 4)    // bytes per batch of vertices = 49152
#define CAND  64              // phase-2 candidate buffer depth per query

typedef unsigned long long ull;

struct Samp { int s[NS]; };   // 4KB by-value kernel parameter

// -------- device scratch (no allocation allowed) --------
__device__ __align__(16) int g_nbr[BATCH * NS * KNBR];

// -------- JAX threefry2x32 (20 rounds), host-usable --------
__host__ __device__ __forceinline__ void threefry2x32(
    uint32_t k0, uint32_t k1, uint32_t x0, uint32_t x1,
    uint32_t* o0, uint32_t* o1)
{
    uint32_t ks2 = k0 ^ k1 ^ 0x1BD11BDAu;
    x0 += k0; x1 += k1;
#define TF_ROT(x, r) (((x) << (r)) | ((x) >> (32 - (r))))
#define TF_R4(a, b, c, d)                       \
    x0 += x1; x1 = TF_ROT(x1, a); x1 ^= x0;     \
    x0 += x1; x1 = TF_ROT(x1, b); x1 ^= x0;     \
    x0 += x1; x1 = TF_ROT(x1, c); x1 ^= x0;     \
    x0 += x1; x1 = TF_ROT(x1, d); x1 ^= x0;
    TF_R4(13, 15, 26, 6);  x0 += k1;  x1 += ks2 + 1u;
    TF_R4(17, 29, 16, 24); x0 += ks2; x1 += k0 + 2u;
    TF_R4(13, 15, 26, 6);  x0 += k0;  x1 += k1 + 3u;
    TF_R4(17, 29, 16, 24); x0 += k1;  x1 += ks2 + 4u;
    TF_R4(13, 15, 26, 6);  x0 += ks2; x1 += k0 + 5u;
#undef TF_R4
#undef TF_ROT
    *o0 = x0; *o1 = x1;
}

// -------- mbarrier / TMA-bulk helpers --------
__device__ __forceinline__ void mbar_init(void* mbar, unsigned count)
{
    unsigned a = (unsigned)__cvta_generic_to_shared(mbar);
    asm volatile("mbarrier.init.shared.b64 [%0], %1;" :: "r"(a), "r"(count) : "memory");
}
__device__ __forceinline__ void mbar_expect_tx(void* mbar, unsigned bytes)
{
    unsigned a = (unsigned)__cvta_generic_to_shared(mbar);
    asm volatile("mbarrier.arrive.expect_tx.shared.b64 _, [%0], %1;"
                 :: "r"(a), "r"(bytes) : "memory");
}
__device__ __forceinline__ void bulk_g2s(void* dst, const void* src,
                                         unsigned bytes, void* mbar)
{
    unsigned d = (unsigned)__cvta_generic_to_shared(dst);
    unsigned m = (unsigned)__cvta_generic_to_shared(mbar);
    asm volatile(
        "cp.async.bulk.shared::cta.global.mbarrier::complete_tx::bytes "
        "[%0], [%1], %2, [%3];"
        :: "r"(d), "l"(src), "r"(bytes), "r"(m) : "memory");
}
__device__ __forceinline__ void mbar_wait(void* mbar, unsigned parity)
{
    unsigned a = (unsigned)__cvta_generic_to_shared(mbar);
    asm volatile(
        "{\n\t.reg .pred P;\n\t"
        "W%=:\n\t"
        "mbarrier.try_wait.parity.acquire.cta.shared::cta.b64 P, [%0], %1, 0x989680;\n\t"
        "@P bra.uni D%=;\n\t"
        "bra.uni W%=;\n\t"
        "D%=:\n\t}"
        :: "r"(a), "r"(parity) : "memory");
}

// ======================= K_knn ==============================================
// 2 queries per warp. Phase 1: branch-free per-lane float top-3 -> 5-pop warp
// merge -> threshold t >= d_(5). Phase 2: rescan, compact d<=t hits to smem,
// exact rank by packed (monotone dist bits, idx).
// block = 128 (4 warps = 8 queries); grid = 4 * 128 = 512 blocks.
// dynamic smem: verts 48KB + buf[8][64] ull (4KB) + cnt[8]
__global__ __launch_bounds__(128) void knn_kernel(const float* __restrict__ Vtx,
                                                  float* __restrict__ out,
                                                  Samp smp)
{
    extern __shared__ __align__(16) float sv[];      // [NV*3] packed xyz
    ull* buf = (ull*)(sv + NV * 3);                  // [8][CAND]
    int* cnt = (int*)(buf + 8 * CAND);               // [8]
    __shared__ __align__(8) ull mbar;

    int b = blockIdx.x >> 7;
    int qg = blockIdx.x & 127;

    if (threadIdx.x == 0) mbar_init(&mbar, 1);
    if (threadIdx.x < 8) cnt[threadIdx.x] = 0;
    __syncthreads();
    if (threadIdx.x == 0) {
        mbar_expect_tx(&mbar, VBB);
        bulk_g2s(sv, Vtx + (size_t)b * NV * 3, VBB, &mbar);
    }
    mbar_wait(&mbar, 0);

    // first q-group block per batch also emits vertices_pool (b,1024,3)
    if (qg == 0) {
        for (int t = threadIdx.x; t < NS * 3; t += 128) {
            int s = t / 3, d = t - 3 * s;
            out[(b * NS + s) * 3 + d] = sv[smp.s[s] * 3 + d];
        }
    }

    int warp = threadIdx.x >> 5;
    int lane = threadIdx.x & 31;
    int s0 = qg * 8 + warp * 2;        // first of this warp's 2 queries

    float qx0, qy0, qz0, qq0, qx1, qy1, qz1, qq1;
    {
        int n0 = smp.s[s0], n1 = smp.s[s0 + 1];
        qx0 = sv[n0 * 3]; qy0 = sv[n0 * 3 + 1]; qz0 = sv[n0 * 3 + 2];
        qx1 = sv[n1 * 3]; qy1 = sv[n1 * 3 + 1]; qz1 = sv[n1 * 3 + 2];
        qq0 = qx0 * qx0 + qy0 * qy0 + qz0 * qz0;
        qq1 = qx1 * qx1 + qy1 * qy1 + qz1 * qz1;
    }

    const float INF = __int_as_float(0x7f800000);
    float a0 = INF, a1 = INF, a2 = INF;   // query 0 per-lane top-3 (sorted)
    float b0 = INF, b1 = INF, b2 = INF;   // query 1

    // ---- Phase 1 ----
    for (int m = lane; m < NV; m += 32) {
        float xm = sv[m * 3], ym = sv[m * 3 + 1], zm = sv[m * 3 + 2];
        float qm = xm * xm + ym * ym + zm * zm;
        float d0 = (-2.0f * (qx0 * xm + qy0 * ym + qz0 * zm) + qm) + qq0;
        float d1 = (-2.0f * (qx1 * xm + qy1 * ym + qz1 * zm) + qm) + qq1;
        // branch-free sorted insert (top-3)
        float c;
        c = fmaxf(a0, d0); a0 = fminf(a0, d0);
        float c2c = fmaxf(a1, c); a1 = fminf(a1, c); a2 = fminf(a2, c2c);
        c = fmaxf(b0, d1); b0 = fminf(b0, d1);
        float c2d = fmaxf(b1, c); b1 = fminf(b1, c); b2 = fminf(b2, c2d);
    }

    // ---- warp merge: pop min 5 times -> thresholds ----
    float t0, t1;
    {
        float h0 = a0, h1 = a1, h2 = a2;
#pragma unroll
        for (int p = 0; p < 5; ++p) {
            float mn = h0;
#pragma unroll
            for (int off = 16; off; off >>= 1)
                mn = fminf(mn, __shfl_xor_sync(0xffffffffu, mn, off));
            bool pop = (h0 == mn);
            h0 = pop ? h1 : h0; h1 = pop ? h2 : h1; h2 = pop ? INF : h2;
            t0 = mn;
        }
        h0 = b0; h1 = b1; h2 = b2;
#pragma unroll
        for (int p = 0; p < 5; ++p) {
            float mn = h0;
#pragma unroll
            for (int off = 16; off; off >>= 1)
                mn = fminf(mn, __shfl_xor_sync(0xffffffffu, mn, off));
            bool pop = (h0 == mn);
            h0 = pop ? h1 : h0; h1 = pop ? h2 : h1; h2 = pop ? INF : h2;
            t1 = mn;
        }
    }

    // ---- Phase 2: collect all m with d <= t ----
    int wq0 = warp * 2, wq1 = warp * 2 + 1;
    for (int m = lane; m < NV; m += 32) {
        float xm = sv[m * 3], ym = sv[m * 3 + 1], zm = sv[m * 3 + 2];
        float qm = xm * xm + ym * ym + zm * zm;
        float d0 = (-2.0f * (qx0 * xm + qy0 * ym + qz0 * zm) + qm) + qq0;
        float d1 = (-2.0f * (qx1 * xm + qy1 * ym + qz1 * zm) + qm) + qq1;
        if (d0 <= t0) {
            unsigned kb = __float_as_uint(d0);
            kb ^= (kb & 0x80000000u) ? 0xffffffffu : 0x80000000u;
            int pos = atomicAdd(&cnt[wq0], 1);
            if (pos < CAND) buf[wq0 * CAND + pos] = ((ull)kb << 32) | (unsigned)m;
        }
        if (d1 <= t1) {
            unsigned kb = __float_as_uint(d1);
            kb ^= (kb & 0x80000000u) ? 0xffffffffu : 0x80000000u;
            int pos = atomicAdd(&cnt[wq1], 1);
            if (pos < CAND) buf[wq1 * CAND + pos] = ((ull)kb << 32) | (unsigned)m;
        }
    }
    __syncwarp();

    // ---- exact rank among candidates; rank0 = global min (self) dropped ----
#pragma unroll
    for (int qi = 0; qi < 2; ++qi) {
        int wq = warp * 2 + qi;
        int n = cnt[wq]; if (n > CAND) n = CAND;
        const ull* bq = &buf[wq * CAND];
        ull va = (lane < n) ? bq[lane] : ~0ULL;
        ull vb = (lane + 32 < n) ? bq[lane + 32] : ~0ULL;
        int ra = 0, rb = 0;
        for (int j = 0; j < n; ++j) {
            ull o = bq[j];               // broadcast LDS
            ra += (o < va); rb += (o < vb);
        }
        int base = (b * NS + (s0 + qi)) * KNBR;
        if (lane < n && ra >= 1 && ra <= KNBR)
            g_nbr[base + ra - 1] = (int)(unsigned)(va & 0xffffffffULL);
        if (lane + 32 < n && rb >= 1 && rb <= KNBR)
            g_nbr[base + rb - 1] = (int)(unsigned)(vb & 0xffffffffULL);
    }
}

// ======================= K_pool =============================================
// One plane per block, TMA bulk stage, scalar LDS gathers.
// grid = 512, block = 256, dynamic smem = 48KB -> 4 blocks/SM.
__global__ __launch_bounds__(256) void pool_kernel(const float* __restrict__ F,
                                                   float* __restrict__ out)
{
    extern __shared__ __align__(16) float sf[];   // [PLF]
    __shared__ __align__(8) ull mbar;

    int pl = blockIdx.x;
    if (threadIdx.x == 0) mbar_init(&mbar, 1);
    __syncthreads();
    if (threadIdx.x == 0) {
        mbar_expect_tx(&mbar, PLB);
        bulk_g2s(sf, F + (size_t)pl * PLB / 4, PLB, &mbar);
    }
    mbar_wait(&mbar, 0);

    int b = pl >> 7;
    const int4* nbr4 = (const int4*)g_nbr + b * NS;
    float* fout = out + BATCH * NS * 3 + (size_t)pl * NS * 3;
#pragma unroll
    for (int r = 0; r < NS / 256; ++r) {
        int t = r * 256 + threadIdx.x;
        int4 nb = __ldg(&nbr4[t]);
        int j0 = nb.x * 3, j1 = nb.y * 3, j2 = nb.z * 3, j3 = nb.w * 3;
        float o0 = fmaxf(fmaxf(sf[j0],     sf[j1]),     fmaxf(sf[j2],     sf[j3]));
        float o1 = fmaxf(fmaxf(sf[j0 + 1], sf[j1 + 1]), fmaxf(sf[j2 + 1], sf[j3 + 1]));
        float o2 = fmaxf(fmaxf(sf[j0 + 2], sf[j1 + 2]), fmaxf(sf[j2 + 2], sf[j3 + 2]));
        fout[t * 3]     = o0;
        fout[t * 3 + 1] = o1;
        fout[t * 3 + 2] = o2;
    }
}

// ======================= host entry =========================================
extern "C" void kernel_launch(void* const* d_in, const int* in_sizes, int n_in,
                              void* d_out, int out_size)
{
    const float* Vtx;
    const float* F;
    if (in_sizes[0] == BATCH * NV * 3) {
        Vtx = (const float*)d_in[0];
        F   = (const float*)d_in[1];
    } else {
        Vtx = (const float*)d_in[1];
        F   = (const float*)d_in[0];
    }

    // ---- host-side permutation (pure arithmetic; runs at capture time) ----
    uint32_t k10, k11, sub_lo[2], sub_hi[2];
    threefry2x32(0u, 42u, 0u, 0u, &k10, &k11);             // round-1 carry key
    threefry2x32(0u, 42u, 0u, 1u, &sub_lo[0], &sub_hi[0]); // round-1 subkey
    threefry2x32(k10, k11, 0u, 1u, &sub_lo[1], &sub_hi[1]);// round-2 subkey

    static ull pk[NV];
    static int rk[2][NV];
    for (int r = 0; r < 2; ++r) {
        for (int i = 0; i < NV; ++i) {
            uint32_t w0, w1;
            threefry2x32(sub_lo[r], sub_hi[r], 0u, (uint32_t)i, &w0, &w1);
            pk[i] = ((ull)(w0 ^ w1) << 32) | (uint32_t)i;
        }
        std::sort(pk, pk + NV);   // index in low bits -> stable rank
        for (int j = 0; j < NV; ++j) rk[r][(uint32_t)pk[j]] = j;
    }
    static Samp h_samp;
    for (int i = 0; i < NV; ++i) {
        int pos = rk[1][rk[0][i]];
        if (pos < NS) h_samp.s[pos] = i;
    }

    int knn_smem = NV * 3 * (int)sizeof(float) + 8 * CAND * (int)sizeof(ull)
                 + 8 * (int)sizeof(int);
    int pool_smem = PLB;
    cudaFuncSetAttribute(knn_kernel,
                         cudaFuncAttributeMaxDynamicSharedMemorySize, knn_smem);
    cudaFuncSetAttribute(pool_kernel,
                         cudaFuncAttributeMaxDynamicSharedMemorySize, pool_smem);

    knn_kernel<<<512, 128, knn_smem>>>(Vtx, (float*)d_out, h_samp);
    pool_kernel<<<512, 256, pool_smem>>>(F, (float*)d_out);
}

// round 7
// speedup vs baseline: 2.3530x; 1.1199x over previous
#include <cuda_runtime.h>
#include <cstdint>
#include <algorithm>

// Problem constants (fixed by dataset shapes)
#define BATCH 4
#define NV    4096
#define NC    128
#define NS    1024   // NV / POOLING_RATE
#define KNBR  4
#define PLF   (NV * 3)        // floats per (b,c) feature plane = 12288
#define PLB   (PLF * 4)       // bytes per plane = 49152
#define VBB   (NV * 3 * 4)    // bytes per batch of vertices = 49152
#define CAND  64              // phase-2 candidate buffer depth per query

typedef unsigned long long ull;

struct Samp { int s[NS]; };   // 4KB by-value kernel parameter

// -------- device scratch (no allocation allowed) --------
__device__ __align__(16) int g_nbr[BATCH * NS * KNBR];

// -------- JAX threefry2x32 (20 rounds), host-usable --------
__host__ __device__ __forceinline__ void threefry2x32(
    uint32_t k0, uint32_t k1, uint32_t x0, uint32_t x1,
    uint32_t* o0, uint32_t* o1)
{
    uint32_t ks2 = k0 ^ k1 ^ 0x1BD11BDAu;
    x0 += k0; x1 += k1;
#define TF_ROT(x, r) (((x) << (r)) | ((x) >> (32 - (r))))
#define TF_R4(a, b, c, d)                       \
    x0 += x1; x1 = TF_ROT(x1, a); x1 ^= x0;     \
    x0 += x1; x1 = TF_ROT(x1, b); x1 ^= x0;     \
    x0 += x1; x1 = TF_ROT(x1, c); x1 ^= x0;     \
    x0 += x1; x1 = TF_ROT(x1, d); x1 ^= x0;
    TF_R4(13, 15, 26, 6);  x0 += k1;  x1 += ks2 + 1u;
    TF_R4(17, 29, 16, 24); x0 += ks2; x1 += k0 + 2u;
    TF_R4(13, 15, 26, 6);  x0 += k0;  x1 += k1 + 3u;
    TF_R4(17, 29, 16, 24); x0 += k1;  x1 += ks2 + 4u;
    TF_R4(13, 15, 26, 6);  x0 += ks2; x1 += k0 + 5u;
#undef TF_R4
#undef TF_ROT
    *o0 = x0; *o1 = x1;
}

// -------- mbarrier / TMA-bulk helpers --------
__device__ __forceinline__ void mbar_init(void* mbar, unsigned count)
{
    unsigned a = (unsigned)__cvta_generic_to_shared(mbar);
    asm volatile("mbarrier.init.shared.b64 [%0], %1;" :: "r"(a), "r"(count) : "memory");
}
__device__ __forceinline__ void mbar_expect_tx(void* mbar, unsigned bytes)
{
    unsigned a = (unsigned)__cvta_generic_to_shared(mbar);
    asm volatile("mbarrier.arrive.expect_tx.shared.b64 _, [%0], %1;"
                 :: "r"(a), "r"(bytes) : "memory");
}
__device__ __forceinline__ void bulk_g2s(void* dst, const void* src,
                                         unsigned bytes, void* mbar)
{
    unsigned d = (unsigned)__cvta_generic_to_shared(dst);
    unsigned m = (unsigned)__cvta_generic_to_shared(mbar);
    asm volatile(
        "cp.async.bulk.shared::cta.global.mbarrier::complete_tx::bytes "
        "[%0], [%1], %2, [%3];"
        :: "r"(d), "l"(src), "r"(bytes), "r"(m) : "memory");
}
__device__ __forceinline__ void mbar_wait(void* mbar, unsigned parity)
{
    unsigned a = (unsigned)__cvta_generic_to_shared(mbar);
    asm volatile(
        "{\n\t.reg .pred P;\n\t"
        "W%=:\n\t"
        "mbarrier.try_wait.parity.acquire.cta.shared::cta.b64 P, [%0], %1, 0x989680;\n\t"
        "@P bra.uni D%=;\n\t"
        "bra.uni W%=;\n\t"
        "D%=:\n\t}"
        :: "r"(a), "r"(parity) : "memory");
}

// ======================= K_knn ==============================================
// 8 queries per block; each query scanned by 2 warps (half the points each),
// 4 queries per warp. Phase 1: per-lane top-1 (fminf) -> 5-pop warp merge ->
// per-half threshold; t = min(halves) >= d_(5). Phase 2: compact d<=t hits,
// exact rank by packed (monotone dist bits, idx). Self = rank 0, dropped.
// block = 128 (4 warps); grid = 4 * 128 = 512 blocks.
__global__ __launch_bounds__(128) void knn_kernel(const float* __restrict__ Vtx,
                                                  float* __restrict__ out,
                                                  Samp smp)
{
    extern __shared__ __align__(16) float sv[];      // [NV*3] packed xyz
    ull*   buf = (ull*)(sv + NV * 3);                // [8][CAND]
    int*   cnt = (int*)(buf + 8 * CAND);             // [8]
    float* tqs = (float*)(cnt + 8);                  // [8][2]
    __shared__ __align__(8) ull mbar;

    int b = blockIdx.x >> 7;
    int qg = blockIdx.x & 127;

    if (threadIdx.x == 0) mbar_init(&mbar, 1);
    if (threadIdx.x < 8) cnt[threadIdx.x] = 0;
    __syncthreads();
    if (threadIdx.x == 0) {
        mbar_expect_tx(&mbar, VBB);
        bulk_g2s(sv, Vtx + (size_t)b * NV * 3, VBB, &mbar);
    }
    mbar_wait(&mbar, 0);

    // first q-group block per batch also emits vertices_pool (b,1024,3)
    if (qg == 0) {
        for (int t = threadIdx.x; t < NS * 3; t += 128) {
            int s = t / 3, d = t - 3 * s;
            out[(b * NS + s) * 3 + d] = sv[smp.s[s] * 3 + d];
        }
    }

    int warp = threadIdx.x >> 5;
    int lane = threadIdx.x & 31;
    int quad = warp >> 1;      // which 4-query group (0/1)
    int half = warp & 1;       // which half of the 4096 points
    int sbase = qg * 8 + quad * 4;

    float qx[4], qy[4], qz[4], qq[4];
#pragma unroll
    for (int qi = 0; qi < 4; ++qi) {
        int n = smp.s[sbase + qi];
        qx[qi] = sv[n * 3]; qy[qi] = sv[n * 3 + 1]; qz[qi] = sv[n * 3 + 2];
        qq[qi] = qx[qi] * qx[qi] + qy[qi] * qy[qi] + qz[qi] * qz[qi];
    }

    const float INF = __int_as_float(0x7f800000);
    float a[4] = {INF, INF, INF, INF};
    int mbeg = half * 2048 + lane, mend = half * 2048 + 2048;

    // ---- Phase 1: per-lane running min per query ----
    for (int m = mbeg; m < mend; m += 32) {
        float xm = sv[m * 3], ym = sv[m * 3 + 1], zm = sv[m * 3 + 2];
        float qm = xm * xm + ym * ym + zm * zm;
#pragma unroll
        for (int qi = 0; qi < 4; ++qi) {
            float inner = qx[qi] * xm + qy[qi] * ym + qz[qi] * zm;
            float d = (-2.0f * inner + qm) + qq[qi];   // matches reference assoc
            a[qi] = fminf(a[qi], d);
        }
    }

    // ---- per-half 5-pop merge -> threshold; min over halves via smem ----
#pragma unroll
    for (int qi = 0; qi < 4; ++qi) {
        float h = a[qi], t = INF;
#pragma unroll
        for (int p = 0; p < 5; ++p) {
            float mn = h;
#pragma unroll
            for (int off = 16; off; off >>= 1)
                mn = fminf(mn, __shfl_xor_sync(0xffffffffu, mn, off));
            h = (h == mn) ? INF : h;
            t = mn;
        }
        if (lane == 0) tqs[(quad * 4 + qi) * 2 + half] = t;
    }
    __syncthreads();

    float tq[4];
#pragma unroll
    for (int qi = 0; qi < 4; ++qi) {
        int q = quad * 4 + qi;
        tq[qi] = fminf(tqs[q * 2], tqs[q * 2 + 1]);
    }

    // ---- Phase 2: collect all m with d <= t (shared counters per query) ----
    for (int m = mbeg; m < mend; m += 32) {
        float xm = sv[m * 3], ym = sv[m * 3 + 1], zm = sv[m * 3 + 2];
        float qm = xm * xm + ym * ym + zm * zm;
#pragma unroll
        for (int qi = 0; qi < 4; ++qi) {
            float inner = qx[qi] * xm + qy[qi] * ym + qz[qi] * zm;
            float d = (-2.0f * inner + qm) + qq[qi];
            if (d <= tq[qi]) {
                unsigned kb = __float_as_uint(d);
                kb ^= (kb & 0x80000000u) ? 0xffffffffu : 0x80000000u; // monotone
                int q = quad * 4 + qi;
                int pos = atomicAdd(&cnt[q], 1);
                if (pos < CAND) buf[q * CAND + pos] = ((ull)kb << 32) | (unsigned)m;
            }
        }
    }
    __syncthreads();

    // ---- exact rank among candidates; warp w ranks queries 2w, 2w+1 ----
#pragma unroll
    for (int k = 0; k < 2; ++k) {
        int q = warp * 2 + k;
        int n = cnt[q]; if (n > CAND) n = CAND;
        const ull* bq = &buf[q * CAND];
        ull va = (lane < n) ? bq[lane] : ~0ULL;
        ull vb = (lane + 32 < n) ? bq[lane + 32] : ~0ULL;
        int ra = 0, rb = 0;
        for (int j = 0; j < n; ++j) {
            ull o = bq[j];               // broadcast LDS
            ra += (o < va); rb += (o < vb);
        }
        int base = (b * NS + (qg * 8 + q)) * KNBR;
        if (lane < n && ra >= 1 && ra <= KNBR)
            g_nbr[base + ra - 1] = (int)(unsigned)(va & 0xffffffffULL);
        if (lane + 32 < n && rb >= 1 && rb <= KNBR)
            g_nbr[base + rb - 1] = (int)(unsigned)(vb & 0xffffffffULL);
    }
}

// ======================= K_pool =============================================
// One plane per block, TMA bulk stage, neighbor indices prefetched before the
// TMA wait. grid = 512, block = 512, dynamic smem = 48KB -> 4 blocks/SM.
__global__ __launch_bounds__(512) void pool_kernel(const float* __restrict__ F,
                                                   float* __restrict__ out)
{
    extern __shared__ __align__(16) float sf[];   // [PLF]
    __shared__ __align__(8) ull mbar;

    int pl = blockIdx.x;
    int b = pl >> 7;
    const int4* nbr4 = (const int4*)g_nbr + b * NS;

    // prefetch neighbor indices (independent of smem contents)
    int t0 = threadIdx.x, t1 = threadIdx.x + 512;
    int4 nbA = __ldg(&nbr4[t0]);
    int4 nbB = __ldg(&nbr4[t1]);

    if (threadIdx.x == 0) mbar_init(&mbar, 1);
    __syncthreads();
    if (threadIdx.x == 0) {
        mbar_expect_tx(&mbar, PLB);
        bulk_g2s(sf, F + (size_t)pl * PLF, PLB, &mbar);
    }
    mbar_wait(&mbar, 0);

    float* fout = out + BATCH * NS * 3 + (size_t)pl * NS * 3;
    {
        int j0 = nbA.x * 3, j1 = nbA.y * 3, j2 = nbA.z * 3, j3 = nbA.w * 3;
        float o0 = fmaxf(fmaxf(sf[j0],     sf[j1]),     fmaxf(sf[j2],     sf[j3]));
        float o1 = fmaxf(fmaxf(sf[j0 + 1], sf[j1 + 1]), fmaxf(sf[j2 + 1], sf[j3 + 1]));
        float o2 = fmaxf(fmaxf(sf[j0 + 2], sf[j1 + 2]), fmaxf(sf[j2 + 2], sf[j3 + 2]));
        fout[t0 * 3]     = o0;
        fout[t0 * 3 + 1] = o1;
        fout[t0 * 3 + 2] = o2;
    }
    {
        int j0 = nbB.x * 3, j1 = nbB.y * 3, j2 = nbB.z * 3, j3 = nbB.w * 3;
        float o0 = fmaxf(fmaxf(sf[j0],     sf[j1]),     fmaxf(sf[j2],     sf[j3]));
        float o1 = fmaxf(fmaxf(sf[j0 + 1], sf[j1 + 1]), fmaxf(sf[j2 + 1], sf[j3 + 1]));
        float o2 = fmaxf(fmaxf(sf[j0 + 2], sf[j1 + 2]), fmaxf(sf[j2 + 2], sf[j3 + 2]));
        fout[t1 * 3]     = o0;
        fout[t1 * 3 + 1] = o1;
        fout[t1 * 3 + 2] = o2;
    }
}

// ======================= host entry =========================================
extern "C" void kernel_launch(void* const* d_in, const int* in_sizes, int n_in,
                              void* d_out, int out_size)
{
    const float* Vtx;
    const float* F;
    if (in_sizes[0] == BATCH * NV * 3) {
        Vtx = (const float*)d_in[0];
        F   = (const float*)d_in[1];
    } else {
        Vtx = (const float*)d_in[1];
        F   = (const float*)d_in[0];
    }

    // ---- host-side permutation (pure arithmetic; runs at capture time) ----
    uint32_t k10, k11, sub_lo[2], sub_hi[2];
    threefry2x32(0u, 42u, 0u, 0u, &k10, &k11);             // round-1 carry key
    threefry2x32(0u, 42u, 0u, 1u, &sub_lo[0], &sub_hi[0]); // round-1 subkey
    threefry2x32(k10, k11, 0u, 1u, &sub_lo[1], &sub_hi[1]);// round-2 subkey

    static ull pk[NV];
    static int rk[2][NV];
    for (int r = 0; r < 2; ++r) {
        for (int i = 0; i < NV; ++i) {
            uint32_t w0, w1;
            threefry2x32(sub_lo[r], sub_hi[r], 0u, (uint32_t)i, &w0, &w1);
            pk[i] = ((ull)(w0 ^ w1) << 32) | (uint32_t)i;
        }
        std::sort(pk, pk + NV);   // index in low bits -> stable rank
        for (int j = 0; j < NV; ++j) rk[r][(uint32_t)pk[j]] = j;
    }
    static Samp h_samp;
    for (int i = 0; i < NV; ++i) {
        int pos = rk[1][rk[0][i]];
        if (pos < NS) h_samp.s[pos] = i;
    }

    int knn_smem = NV * 3 * (int)sizeof(float) + 8 * CAND * (int)sizeof(ull)
                 + 8 * (int)sizeof(int) + 16 * (int)sizeof(float);
    int pool_smem = PLB;
    cudaFuncSetAttribute(knn_kernel,
                         cudaFuncAttributeMaxDynamicSharedMemorySize, knn_smem);
    cudaFuncSetAttribute(pool_kernel,
                         cudaFuncAttributeMaxDynamicSharedMemorySize, pool_smem);

    knn_kernel<<<512, 128, knn_smem>>>(Vtx, (float*)d_out, h_samp);
    pool_kernel<<<512, 512, pool_smem>>>(F, (float*)d_out);
}